// round 1
// baseline (speedup 1.0000x reference)
#include <cuda_runtime.h>
#include <cstdint>

#define CAT     160
#define HID     128
#define OUTD    64
#define TILE_E  128
#define THREADS 256
#define KC      32
#define XS_STRIDE 33
#define HS_STRIDE 133

// dynamic smem layout (in floats)
#define HS_OFF   0
#define HS_SIZE  (TILE_E * HS_STRIDE)          // 17024
#define XS_OFF   HS_SIZE
#define XS_SIZE  (TILE_E * XS_STRIDE)          // 4224
#define WS_OFF   (XS_OFF + XS_SIZE)
#define WS_SIZE  (KC * HID)                    // 4096
#define W2S_OFF  XS_OFF                        // stage-2 reuses Xs/Ws region
#define W2S_SIZE (HID * OUTD)                  // 8192
#define SMEM_FLOATS (XS_OFF + (XS_SIZE + WS_SIZE > W2S_SIZE ? XS_SIZE + WS_SIZE : W2S_SIZE))
#define SMEM_BYTES  (SMEM_FLOATS * 4)

__device__ __forceinline__ unsigned long long pack2(float x) {
    unsigned long long r;
    unsigned xi = __float_as_uint(x);
    asm("mov.b64 %0, {%1, %1};" : "=l"(r) : "r"(xi));
    return r;
}

__device__ __forceinline__ void fma2(unsigned long long& d,
                                     unsigned long long a,
                                     unsigned long long b) {
    asm("fma.rn.f32x2 %0, %1, %2, %0;" : "+l"(d) : "l"(a), "l"(b));
}

__device__ __forceinline__ void unpack2(unsigned long long v, float& lo, float& hi) {
    asm("mov.b64 {%0, %1}, %2;" : "=f"(lo), "=f"(hi) : "l"(v));
}

__global__ void __launch_bounds__(THREADS)
edge_mlp_kernel(const float* __restrict__ src,
                const float* __restrict__ dst,
                const float* __restrict__ ea,
                const float* __restrict__ W1,
                const float* __restrict__ b1,
                const float* __restrict__ W2,
                const float* __restrict__ b2,
                float* __restrict__ out,
                int E)
{
    extern __shared__ float sm[];
    float* Hs  = sm + HS_OFF;
    float* Xs  = sm + XS_OFF;
    float* Ws  = sm + WS_OFF;
    float* W2s = sm + W2S_OFF;

    const int tid = threadIdx.x;
    const int e0  = blockIdx.x * TILE_E;

    // ---------------- Stage 1: H = relu(X @ W1 + b1), X = [src|dest|edge] ----
    const int tx = tid & 15, ty = tid >> 4;
    const int r0 = ty * 8,   j0 = tx * 8;

    unsigned long long acc[8][4];
    #pragma unroll
    for (int r = 0; r < 8; r++)
        #pragma unroll
        for (int p = 0; p < 4; p++) acc[r][p] = 0ull;

    for (int ch = 0; ch < 5; ch++) {
        const float* base; int ld, off;
        if (ch < 2)      { base = src; ld = 64; off = ch * 32; }
        else if (ch < 4) { base = dst; ld = 64; off = (ch - 2) * 32; }
        else             { base = ea;  ld = 32; off = 0; }

        // load X chunk [TILE_E x 32]
        #pragma unroll
        for (int i = tid; i < TILE_E * KC; i += THREADS) {
            int r = i >> 5, c = i & 31;
            int e = e0 + r;
            float v = (e < E) ? base[(long)e * ld + off + c] : 0.f;
            Xs[r * XS_STRIDE + c] = v;
        }
        // load W1 chunk [32 x 128]
        const int k0 = ch * KC;
        #pragma unroll
        for (int i = tid; i < KC * HID; i += THREADS) {
            int kk = i >> 7, j = i & 127;
            Ws[kk * HID + j] = W1[(k0 + kk) * HID + j];
        }
        __syncthreads();

        #pragma unroll 8
        for (int kk = 0; kk < KC; kk++) {
            const unsigned long long* wp =
                (const unsigned long long*)(Ws + kk * HID + j0);
            unsigned long long w0 = wp[0], w1 = wp[1], w2 = wp[2], w3 = wp[3];
            #pragma unroll
            for (int r = 0; r < 8; r++) {
                unsigned long long xx = pack2(Xs[(r0 + r) * XS_STRIDE + kk]);
                fma2(acc[r][0], xx, w0);
                fma2(acc[r][1], xx, w1);
                fma2(acc[r][2], xx, w2);
                fma2(acc[r][3], xx, w3);
            }
        }
        __syncthreads();
    }

    // bias + relu -> Hs
    float bj[8];
    #pragma unroll
    for (int jj = 0; jj < 8; jj++) bj[jj] = b1[j0 + jj];
    #pragma unroll
    for (int r = 0; r < 8; r++) {
        #pragma unroll
        for (int p = 0; p < 4; p++) {
            float lo, hi;
            unpack2(acc[r][p], lo, hi);
            lo = fmaxf(lo + bj[2 * p],     0.f);
            hi = fmaxf(hi + bj[2 * p + 1], 0.f);
            Hs[(r0 + r) * HS_STRIDE + j0 + 2 * p]     = lo;
            Hs[(r0 + r) * HS_STRIDE + j0 + 2 * p + 1] = hi;
        }
    }

    // load W2 [128 x 64] into the region previously used by Xs/Ws
    #pragma unroll
    for (int i = tid; i < HID * OUTD; i += THREADS)
        W2s[i] = W2[i];
    __syncthreads();

    // ---------------- Stage 2: out = H @ W2 + b2 -----------------------------
    const int tx2 = tid & 7, ty2 = tid >> 3;
    const int rr0 = ty2 * 4, c0  = tx2 * 8;

    unsigned long long acc2[4][4];
    #pragma unroll
    for (int r = 0; r < 4; r++)
        #pragma unroll
        for (int p = 0; p < 4; p++) acc2[r][p] = 0ull;

    #pragma unroll 8
    for (int k = 0; k < HID; k++) {
        const unsigned long long* wp =
            (const unsigned long long*)(W2s + k * OUTD + c0);
        unsigned long long w0 = wp[0], w1 = wp[1], w2 = wp[2], w3 = wp[3];
        #pragma unroll
        for (int r = 0; r < 4; r++) {
            unsigned long long xx = pack2(Hs[(rr0 + r) * HS_STRIDE + k]);
            fma2(acc2[r][0], xx, w0);
            fma2(acc2[r][1], xx, w1);
            fma2(acc2[r][2], xx, w2);
            fma2(acc2[r][3], xx, w3);
        }
    }

    float bc[8];
    #pragma unroll
    for (int jj = 0; jj < 8; jj++) bc[jj] = b2[c0 + jj];

    #pragma unroll
    for (int r = 0; r < 4; r++) {
        int e = e0 + rr0 + r;
        if (e < E) {
            float v[8];
            #pragma unroll
            for (int p = 0; p < 4; p++) {
                float lo, hi;
                unpack2(acc2[r][p], lo, hi);
                v[2 * p]     = lo + bc[2 * p];
                v[2 * p + 1] = hi + bc[2 * p + 1];
            }
            float4* o = (float4*)(out + (long)e * OUTD + c0);
            o[0] = make_float4(v[0], v[1], v[2], v[3]);
            o[1] = make_float4(v[4], v[5], v[6], v[7]);
        }
    }
}

extern "C" void kernel_launch(void* const* d_in, const int* in_sizes, int n_in,
                              void* d_out, int out_size) {
    const float* src = (const float*)d_in[0];
    const float* dst = (const float*)d_in[1];
    const float* ea  = (const float*)d_in[2];
    // d_in[3] = u, d_in[4] = batch : unused by the reference math
    const float* W1  = (const float*)d_in[5];
    const float* b1  = (const float*)d_in[6];
    const float* W2  = (const float*)d_in[7];
    const float* b2  = (const float*)d_in[8];
    float* out = (float*)d_out;

    const int E = in_sizes[0] / 64;  // src is [E, 64]

    cudaFuncSetAttribute(edge_mlp_kernel,
                         cudaFuncAttributeMaxDynamicSharedMemorySize, SMEM_BYTES);

    const int grid = (E + TILE_E - 1) / TILE_E;
    edge_mlp_kernel<<<grid, THREADS, SMEM_BYTES>>>(src, dst, ea, W1, b1, W2, b2,
                                                   out, E);
}